// round 15
// baseline (speedup 1.0000x reference)
#include <cuda_runtime.h>
#include <cstdint>

#define BETA_C (8.0f / 3.0f)

// ---------------- scalar step (tail kernel only) ----------------
__device__ __forceinline__ void lorenz_step(float yin0, float yin1, float yin2,
                                            float& o0, float& o1, float& o2) {
    const float h  = 0.01f;
    const float c1 = 0.5f * h;
    const float c2 = h * h / 6.0f;
    const float c3 = h * h * h / 8.0f;
    const float c4 = h * h * h / 24.0f;

    float y0 = 10.0f * yin0, y1 = 10.0f * yin1, y2 = 10.0f * yin2;
    float f0 = 10.0f * y1 - 10.0f * y0;
    float f1 = 28.0f * y0 - y0 * y2 - y1;
    float f2 = y0 * y1 - BETA_C * y2;
    float j00 = 28.0f - y2;
    float dff0 = 10.0f * f1 - 10.0f * f0;
    float dff1 = j00 * f0 - f1 - y0 * f2;
    float dff2 = y1 * f0 + y0 * f1 - BETA_C * f2;
    float dfdff0 = 10.0f * dff1 - 10.0f * dff0;
    float dfdff1 = j00 * dff0 - dff1 - y0 * dff2;
    float dfdff2 = y1 * dff0 + y0 * dff1 - BETA_C * dff2;
    float ddfff1 = -2.0f * f0 * f2;
    float ddfff2 =  2.0f * f0 * f1;
    float ddfdfff1 = -dff0 * f2 - dff2 * f0;
    float ddfdfff2 =  dff0 * f1 + dff1 * f0;
    float dfddfff0 = 10.0f * ddfff1;
    float dfddfff1 = -ddfff1 - y0 * ddfff2;
    float dfddfff2 = y0 * f1 - BETA_C * ddfff2;
    float dfdfdff0 = 10.0f * dfdff1 - 10.0f * dfdff0;
    float dfdfdff1 = j00 * dfdff0 - dfdff1 - y0 * dfdff2;
    float dfdfdff2 = y1 * dfdff0 + y0 * dfdff1 - BETA_C * dfdff2;
    o0 = (f0 + c1 * dff0 + c2 * dfdff0 + c4 * (dfddfff0 + dfdfdff0)) * 0.1f;
    o1 = (f1 + c1 * dff1 + c2 * (ddfff1 + dfdff1)
             + c3 * ddfdfff1 + c4 * (dfddfff1 + dfdfdff1)) * 0.1f;
    o2 = (f2 + c1 * dff2 + c2 * (ddfff2 + dfdff2)
             + c3 * ddfdfff2 + c4 * (dfddfff2 + dfdfdff2)) * 0.1f;
}

// ---------------- packed f32x2 primitives ----------------
typedef unsigned long long u64;

__device__ __forceinline__ u64 f2pk(float lo, float hi) {
    u64 d;
    asm("mov.b64 %0, {%1, %2};" : "=l"(d)
        : "r"(__float_as_uint(lo)), "r"(__float_as_uint(hi)));
    return d;
}
__device__ __forceinline__ void f2up(u64 v, float& lo, float& hi) {
    uint32_t a, b;
    asm("mov.b64 {%0, %1}, %2;" : "=r"(a), "=r"(b) : "l"(v));
    lo = __uint_as_float(a); hi = __uint_as_float(b);
}
__device__ __forceinline__ u64 f2mul(u64 a, u64 b) {
    u64 d; asm("mul.rn.f32x2 %0, %1, %2;" : "=l"(d) : "l"(a), "l"(b)); return d;
}
__device__ __forceinline__ u64 f2add(u64 a, u64 b) {
    u64 d; asm("add.rn.f32x2 %0, %1, %2;" : "=l"(d) : "l"(a), "l"(b)); return d;
}
__device__ __forceinline__ u64 f2fma(u64 a, u64 b, u64 c) {
    u64 d; asm("fma.rn.f32x2 %0, %1, %2, %3;" : "=l"(d) : "l"(a), "l"(b), "l"(c)); return d;
}

struct PkConsts {
    u64 K10, K28, KnB, Kn2, K2, Kn1, K01, Kc1, Kc2, Kc3, Knc3, Kc4;
};
__device__ __forceinline__ PkConsts make_consts() {
    const float h = 0.01f;
    PkConsts k;
    k.K10 = f2pk(10.0f, 10.0f);
    k.K28 = f2pk(28.0f, 28.0f);
    k.KnB = f2pk(-BETA_C, -BETA_C);
    k.Kn2 = f2pk(-2.0f, -2.0f);
    k.K2  = f2pk(2.0f, 2.0f);
    k.Kn1 = f2pk(-1.0f, -1.0f);
    k.K01 = f2pk(0.1f, 0.1f);
    k.Kc1 = f2pk(0.5f * h, 0.5f * h);
    k.Kc2 = f2pk(h * h / 6.0f, h * h / 6.0f);
    k.Kc3 = f2pk(h * h * h / 8.0f, h * h * h / 8.0f);
    k.Knc3 = f2pk(-h * h * h / 8.0f, -h * h * h / 8.0f);
    k.Kc4 = f2pk(h * h * h / 24.0f, h * h * h / 24.0f);
    return k;
}

#define F2SUB(a, b) f2fma((b), k.Kn1, (a))

// Packed Lorenz Taylor step: TWO independent triples (lo/hi halves).
__device__ __forceinline__ void lorenz2(const PkConsts& k,
                                        u64& x0, u64& x1, u64& x2) {
    u64 y0 = f2mul(k.K10, x0);
    u64 y1 = f2mul(k.K10, x1);
    u64 y2 = f2mul(k.K10, x2);

    u64 f0 = f2mul(k.K10, F2SUB(y1, y0));
    u64 j  = F2SUB(k.K28, y2);
    u64 f1 = F2SUB(f2mul(y0, j), y1);
    u64 f2v = f2fma(y0, y1, f2mul(k.KnB, y2));

    u64 dff0 = f2mul(k.K10, F2SUB(f1, f0));
    u64 dff1 = F2SUB(f2mul(j, f0), f2fma(y0, f2v, f1));
    u64 dff2 = f2fma(y1, f0, f2fma(y0, f1, f2mul(k.KnB, f2v)));

    u64 dfdff0 = f2mul(k.K10, F2SUB(dff1, dff0));
    u64 dfdff1 = F2SUB(f2mul(j, dff0), f2fma(y0, dff2, dff1));
    u64 dfdff2 = f2fma(y1, dff0, f2fma(y0, dff1, f2mul(k.KnB, dff2)));

    u64 ddfff1 = f2mul(k.Kn2, f2mul(f0, f2v));
    u64 ddfff2 = f2mul(k.K2,  f2mul(f0, f1));

    u64 nddfdfff1 = f2fma(dff0, f2v, f2mul(dff2, f0));   // = -ddfdfff1
    u64 ddfdfff2  = f2fma(dff0, f1,  f2mul(dff1, f0));

    u64 dfddfff0  = f2mul(k.K10, ddfff1);
    u64 ndfddfff1 = f2fma(y0, ddfff2, ddfff1);           // = -dfddfff1
    u64 dfddfff2  = f2fma(y0, f1, f2mul(k.KnB, ddfff2)); // ref quirk

    u64 dfdfdff0 = f2mul(k.K10, F2SUB(dfdff1, dfdff0));
    u64 dfdfdff1 = F2SUB(f2mul(j, dfdff0), f2fma(y0, dfdff2, dfdff1));
    u64 dfdfdff2 = f2fma(y1, dfdff0, f2fma(y0, dfdff1, f2mul(k.KnB, dfdff2)));

    u64 acc = f2fma(k.Kc1, dff0, f0);
    acc = f2fma(k.Kc2, dfdff0, acc);
    acc = f2fma(k.Kc4, f2add(dfddfff0, dfdfdff0), acc);
    x0 = f2mul(k.K01, acc);

    acc = f2fma(k.Kc1, dff1, f1);
    acc = f2fma(k.Kc2, f2add(ddfff1, dfdff1), acc);
    acc = f2fma(k.Knc3, nddfdfff1, acc);
    acc = f2fma(k.Kc4, F2SUB(dfdfdff1, ndfddfff1), acc);
    x1 = f2mul(k.K01, acc);

    acc = f2fma(k.Kc1, dff2, f2v);
    acc = f2fma(k.Kc2, f2add(ddfff2, dfdff2), acc);
    acc = f2fma(k.Kc3, ddfdfff2, acc);
    acc = f2fma(k.Kc4, f2add(dfddfff2, dfdfdff2), acc);
    x2 = f2mul(k.K01, acc);
}

__device__ __forceinline__ void pack3(const float4& a, const float4& b,
                                      const float4& c, u64* u, u64* v) {
    u[0] = f2pk(a.x, a.w);
    u[1] = f2pk(a.y, b.x);
    u[2] = f2pk(a.z, b.y);
    v[0] = f2pk(b.z, c.y);
    v[1] = f2pk(b.w, c.z);
    v[2] = f2pk(c.x, c.w);
}
__device__ __forceinline__ void unpack3(const u64* u, const u64* v,
                                        float4& a, float4& b, float4& c) {
    f2up(u[0], a.x, a.w);
    f2up(u[1], a.y, b.x);
    f2up(u[2], a.z, b.y);
    f2up(v[0], b.z, c.y);
    f2up(v[1], b.w, c.z);
    f2up(v[2], c.x, c.w);
}

__device__ __forceinline__ float4 shfl4(float4 v, int src) {
    float4 r;
    r.x = __shfl_sync(0xFFFFFFFFu, v.x, src);
    r.y = __shfl_sync(0xFFFFFFFFu, v.y, src);
    r.z = __shfl_sync(0xFFFFFFFFu, v.z, src);
    r.w = __shfl_sync(0xFFFFFFFFu, v.w, src);
    return r;
}
__device__ __forceinline__ float4 sel3(int i, const float4& p0,
                                       const float4& p1, const float4& p2) {
    return (i == 0) ? p0 : (i == 1) ? p1 : p2;
}

// Register-shuffle transpose at float4 granularity. Warp tile = 96 float4
// (384 floats = 128 triples). Coalesced LDG.128/STG.128 only; the AoS<->
// per-thread-triple transpose uses 3 float4 shuffle rounds per direction
// (gcd(3,32)=1 -> bijective lane maps, verified in R8). No smem, no barriers.
__global__ void __launch_bounds__(256) IE_LS_kernel(
    const float4* __restrict__ in, float4* __restrict__ out) {
    const int lane = threadIdx.x & 31;
    const int warp = threadIdx.x >> 5;
    const long long base = (long long)(blockIdx.x * 8 + warp) * 96;

    // Transpose maps (element space = float4 indices [0,96), stride 3):
    const int t0 = (11 * (lane - 0)) & 31;
    const int t1 = (11 * (lane - 1)) & 31;
    const int t2 = (11 * (lane - 2)) & 31;
    const int i0 = (3 * t0 + 0) >> 5;
    const int i1 = (3 * t1 + 1) >> 5;
    const int i2 = (3 * t2 + 2) >> 5;
    const int g0 = (3 * lane + 0) & 31;
    const int g1 = (3 * lane + 1) & 31;
    const int g2 = (3 * lane + 2) & 31;

    // Coalesced loads.
    float4 p0 = in[base + lane];
    float4 p1 = in[base + 32 + lane];
    float4 p2 = in[base + 64 + lane];

    // Gather: lane ends owning float4s 3L, 3L+1, 3L+2 (floats 12L..12L+11).
    float4 a = shfl4(sel3(i0, p0, p1, p2), g0);
    float4 b = shfl4(sel3(i1, p0, p1, p2), g1);
    float4 c = shfl4(sel3(i2, p0, p1, p2), g2);

    const PkConsts k = make_consts();
    u64 U[3], V[3];
    pack3(a, b, c, U, V);
    lorenz2(k, U[0], U[1], U[2]);
    lorenz2(k, V[0], V[1], V[2]);
    unpack3(U, V, a, b, c);

    // Scatter back to coalesced layout.
    float4 v0 = shfl4(a, t0);
    float4 v1 = shfl4(b, t1);
    float4 v2 = shfl4(c, t2);
    float4 q0 = (i0 == 0) ? v0 : (i1 == 0) ? v1 : v2;
    float4 q1 = (i0 == 1) ? v0 : (i1 == 1) ? v1 : v2;
    float4 q2 = (i0 == 2) ? v0 : (i1 == 2) ? v1 : v2;

    out[base + lane]      = q0;
    out[base + 32 + lane] = q1;
    out[base + 64 + lane] = q2;
}

// Tail kernel for leftover triples (not hit for the bench shape).
__global__ void IE_LS_tail_kernel(const float* __restrict__ in,
                                  float* __restrict__ out,
                                  int start_triple, int n_triples) {
    int t = start_triple + blockIdx.x * blockDim.x + threadIdx.x;
    if (t >= n_triples) return;
    float o0, o1, o2;
    lorenz_step(in[3 * t], in[3 * t + 1], in[3 * t + 2], o0, o1, o2);
    out[3 * t] = o0; out[3 * t + 1] = o1; out[3 * t + 2] = o2;
}

extern "C" void kernel_launch(void* const* d_in, const int* in_sizes, int n_in,
                              void* d_out, int out_size) {
    const float* in = (const float*)d_in[0];
    float* out = (float*)d_out;
    int n_elems = in_sizes[0];             // 12582912 = 4194304 * 3
    int n_triples = n_elems / 3;
    int n_blocks = n_elems / 3072;         // 3072 floats (1024 triples) per block

    if (n_blocks > 0) {
        IE_LS_kernel<<<n_blocks, 256>>>((const float4*)in, (float4*)out);
    }
    int done = n_blocks * 1024;
    int rem = n_triples - done;
    if (rem > 0) {
        IE_LS_tail_kernel<<<(rem + 255) / 256, 256>>>(in, out, done, n_triples);
    }
}

// round 16
// speedup vs baseline: 1.0101x; 1.0101x over previous
#include <cuda_runtime.h>
#include <cstdint>

#define BETA_C (8.0f / 3.0f)

__device__ __forceinline__ void lorenz_step(float yin0, float yin1, float yin2,
                                            float& o0, float& o1, float& o2) {
    const float h  = 0.01f;
    const float c1 = 0.5f * h;            // a0*h
    const float c2 = h * h / 6.0f;        // a1*h^2 == a2*h^2
    const float c3 = h * h * h / 8.0f;    // a4*h^3 (=3/24)
    const float c4 = h * h * h / 24.0f;   // a5*h^3 == a6*h^3

    float y0 = 10.0f * yin0, y1 = 10.0f * yin1, y2 = 10.0f * yin2;

    float f0 = 10.0f * y1 - 10.0f * y0;
    float f1 = 28.0f * y0 - y0 * y2 - y1;
    float f2 = y0 * y1 - BETA_C * y2;

    float j00 = 28.0f - y2;

    float dff0 = 10.0f * f1 - 10.0f * f0;
    float dff1 = j00 * f0 - f1 - y0 * f2;
    float dff2 = y1 * f0 + y0 * f1 - BETA_C * f2;

    float dfdff0 = 10.0f * dff1 - 10.0f * dff0;
    float dfdff1 = j00 * dff0 - dff1 - y0 * dff2;
    float dfdff2 = y1 * dff0 + y0 * dff1 - BETA_C * dff2;

    float ddfff1 = -2.0f * f0 * f2;
    float ddfff2 =  2.0f * f0 * f1;

    float ddfdfff1 = -dff0 * f2 - dff2 * f0;
    float ddfdfff2 =  dff0 * f1 + dff1 * f0;

    float dfddfff0 = 10.0f * ddfff1;
    float dfddfff1 = -ddfff1 - y0 * ddfff2;
    float dfddfff2 = y0 * f1 - BETA_C * ddfff2;   // ref quirk

    float dfdfdff0 = 10.0f * dfdff1 - 10.0f * dfdff0;
    float dfdfdff1 = j00 * dfdff0 - dfdff1 - y0 * dfdff2;
    float dfdfdff2 = y1 * dfdff0 + y0 * dfdff1 - BETA_C * dfdff2;

    o0 = (f0 + c1 * dff0 + c2 * dfdff0 + c4 * (dfddfff0 + dfdfdff0)) * 0.1f;
    o1 = (f1 + c1 * dff1 + c2 * (ddfff1 + dfdff1)
             + c3 * ddfdfff1 + c4 * (dfddfff1 + dfdfdff1)) * 0.1f;
    o2 = (f2 + c1 * dff2 + c2 * (ddfff2 + dfdff2)
             + c3 * ddfdfff2 + c4 * (dfddfff2 + dfdfdff2)) * 0.1f;
}

__device__ __forceinline__ float4 shfl4(float4 v, int src) {
    float4 r;
    r.x = __shfl_sync(0xFFFFFFFFu, v.x, src);
    r.y = __shfl_sync(0xFFFFFFFFu, v.y, src);
    r.z = __shfl_sync(0xFFFFFFFFu, v.z, src);
    r.w = __shfl_sync(0xFFFFFFFFu, v.w, src);
    return r;
}
__device__ __forceinline__ float4 sel3(int i, const float4& p0,
                                       const float4& p1, const float4& p2) {
    return (i == 0) ? p0 : (i == 1) ? p1 : p2;
}

// Process one 96-float4 warp tile held in registers p0,p1,p2.
// Maps (t*,i*,g*) are precomputed once per thread and reused for both tiles.
__device__ __forceinline__ void do_tile(
    float4& p0, float4& p1, float4& p2,
    int t0, int t1, int t2, int i0, int i1, int i2, int g0, int g1, int g2) {
    // Gather: lane ends owning float4s 3L..3L+2 (floats 12L..12L+11 = 4 triples).
    float4 a = shfl4(sel3(i0, p0, p1, p2), g0);
    float4 b = shfl4(sel3(i1, p0, p1, p2), g1);
    float4 c = shfl4(sel3(i2, p0, p1, p2), g2);

    float v[12] = {a.x, a.y, a.z, a.w, b.x, b.y, b.z, b.w, c.x, c.y, c.z, c.w};
#pragma unroll
    for (int q = 0; q < 4; q++)
        lorenz_step(v[3 * q + 0], v[3 * q + 1], v[3 * q + 2],
                    v[3 * q + 0], v[3 * q + 1], v[3 * q + 2]);
    a = make_float4(v[0], v[1], v[2], v[3]);
    b = make_float4(v[4], v[5], v[6], v[7]);
    c = make_float4(v[8], v[9], v[10], v[11]);

    // Scatter back to coalesced layout.
    float4 w0 = shfl4(a, t0);
    float4 w1 = shfl4(b, t1);
    float4 w2 = shfl4(c, t2);
    p0 = (i0 == 0) ? w0 : (i1 == 0) ? w1 : w2;
    p1 = (i0 == 1) ? w0 : (i1 == 1) ? w1 : w2;
    p2 = (i0 == 2) ? w0 : (i1 == 2) ? w1 : w2;
}

// Register-shuffle transpose at float4 granularity, two 96-float4 tiles per
// warp (768 floats = 256 triples). 6 front-batched LDG.128 per thread for
// MLP; transpose maps computed once and shared by both tiles. No smem.
__global__ void __launch_bounds__(256) IE_LS_kernel(
    const float4* __restrict__ in, float4* __restrict__ out) {
    const int lane = threadIdx.x & 31;
    const int warp = threadIdx.x >> 5;
    const long long base = (long long)(blockIdx.x * 8 + warp) * 192;

    // Transpose maps (float4-index space [0,96), stride 3; gcd(3,32)=1):
    const int t0 = (11 * (lane - 0)) & 31;
    const int t1 = (11 * (lane - 1)) & 31;
    const int t2 = (11 * (lane - 2)) & 31;
    const int i0 = (3 * t0 + 0) >> 5;
    const int i1 = (3 * t1 + 1) >> 5;
    const int i2 = (3 * t2 + 2) >> 5;
    const int g0 = (3 * lane + 0) & 31;
    const int g1 = (3 * lane + 1) & 31;
    const int g2 = (3 * lane + 2) & 31;

    // Front-batched coalesced loads for both tiles (6 LDG.128 in flight).
    float4 a0 = in[base + lane];
    float4 a1 = in[base + 32 + lane];
    float4 a2 = in[base + 64 + lane];
    float4 b0 = in[base + 96 + lane];
    float4 b1 = in[base + 128 + lane];
    float4 b2 = in[base + 160 + lane];

    do_tile(a0, a1, a2, t0, t1, t2, i0, i1, i2, g0, g1, g2);
    out[base + lane]      = a0;
    out[base + 32 + lane] = a1;
    out[base + 64 + lane] = a2;

    do_tile(b0, b1, b2, t0, t1, t2, i0, i1, i2, g0, g1, g2);
    out[base + 96 + lane]  = b0;
    out[base + 128 + lane] = b1;
    out[base + 160 + lane] = b2;
}

// Tail kernel for leftover triples (not hit for the bench shape).
__global__ void IE_LS_tail_kernel(const float* __restrict__ in,
                                  float* __restrict__ out,
                                  int start_triple, int n_triples) {
    int t = start_triple + blockIdx.x * blockDim.x + threadIdx.x;
    if (t >= n_triples) return;
    float o0, o1, o2;
    lorenz_step(in[3 * t], in[3 * t + 1], in[3 * t + 2], o0, o1, o2);
    out[3 * t] = o0; out[3 * t + 1] = o1; out[3 * t + 2] = o2;
}

extern "C" void kernel_launch(void* const* d_in, const int* in_sizes, int n_in,
                              void* d_out, int out_size) {
    const float* in = (const float*)d_in[0];
    float* out = (float*)d_out;
    int n_elems = in_sizes[0];             // 12582912 = 4194304 * 3
    int n_triples = n_elems / 3;
    int n_blocks = n_elems / 6144;         // 6144 floats (2048 triples) per block

    if (n_blocks > 0) {
        IE_LS_kernel<<<n_blocks, 256>>>((const float4*)in, (float4*)out);
    }
    int done = n_blocks * 2048;
    int rem = n_triples - done;
    if (rem > 0) {
        IE_LS_tail_kernel<<<(rem + 255) / 256, 256>>>(in, out, done, n_triples);
    }
}